// round 6
// baseline (speedup 1.0000x reference)
#include <cuda_runtime.h>

// out[b,c,d] = 0.5 * sum_p W[z(b),c,p] * t[p,b,c,d]   (z(b) = one-hot argmax)
//   t:  [P=4, B, C=256, L=3] fp32   na: [B, Z=64] fp32   W: [Z=64, C=256, P=4]
//   out:[B, C=256, L=3]
//
// HBM-bound streamer (781 MB floor), measured 88.9% DRAM at R5. This round:
// PERSISTENT grid-stride form — 1184 CTAs (8/SM, full 1536-thread occupancy)
// each loop ~42 nodes. Removes ~49K CTA launch/drain boundaries (where the
// per-CTA load pipeline is empty) and hoists loop-invariant per-thread setup.
// Next iteration's t-loads issue right after the previous store (stores are
// fire-and-forget), keeping DRAM continuously fed.

#define Z_DIM 64
#define C_DIM 256
#define P_DIM 4
#define L_DIM 3
#define CL    (C_DIM * L_DIM)   // 768 floats per (p,b) plane / out row
#define CP    (C_DIM * P_DIM)   // 1024 floats per W[z] row
#define NTHR  (CL / 4)          // 192 threads: one float4 per thread
#define NCTA_PER_SM 8           // 192*8 = 1536 threads/SM (max) -> regs <= 42

__global__ void __launch_bounds__(NTHR, NCTA_PER_SM)
ecwl_kernel(const float* __restrict__ t,
            const float* __restrict__ na,
            const float* __restrict__ W,
            float*       __restrict__ out,
            int B)
{
    const int tid  = threadIdx.x;
    const int lane = tid & 31;
    const int e0   = tid * 4;

    // Loop-invariant per-thread setup (hoisted out of the per-node work).
    const int c0 = e0 / 3;
    const bool s1 = ((e0 + 1) / 3 == c0);
    const bool s2 = ((e0 + 2) / 3 == c0);
    const bool s3 = ((e0 + 3) / 3 == c0);
    const int stride = gridDim.x;

    for (int b = blockIdx.x; b < B; b += stride) {
        // 1) Issue all 4 independent t-plane loads FIRST (addresses don't
        //    depend on the routing index); they overlap the na resolve and,
        //    across iterations, the previous store.
        float4 v[P_DIM];
        #pragma unroll
        for (int p = 0; p < P_DIM; ++p)
            v[p] = *reinterpret_cast<const float4*>(
                t + ((size_t)p * B + b) * CL + e0);

        // 2) Warp-local routing resolve (no barrier, no smem): every warp
        //    reads the 64-float one-hot row (L1-hot for warps 1..5) and
        //    extracts the hot index via ballot.
        const float x0 = __ldg(na + (size_t)b * Z_DIM + lane);
        const float x1 = __ldg(na + (size_t)b * Z_DIM + 32 + lane);
        const unsigned m0 = __ballot_sync(0xFFFFFFFFu, x0 > 0.5f);
        const unsigned m1 = __ballot_sync(0xFFFFFFFFu, x1 > 0.5f);
        const int zi = m0 ? (__ffs(m0) - 1) : (32 + __ffs(m1) - 1);

        // 3) Weight row (L1/L2-hot: 64 rows, reused 50000x). float4 = the 4
        //    path-weights of one channel; a thread's t-float4 straddles <=2
        //    channels (L=3).
        const float4* Wr = reinterpret_cast<const float4*>(W + (size_t)zi * CP);
        const float4 w0 = __ldg(Wr + c0);
        const float4 w1 = __ldg(Wr + c0 + 1);   // c0 <= 254, in-bounds

        const float wA[4] = {w0.x, w0.y, w0.z, w0.w};
        const float wB[4] = {w1.x, w1.y, w1.z, w1.w};

        float a0 = 0.f, a1 = 0.f, a2 = 0.f, a3 = 0.f;
        #pragma unroll
        for (int p = 0; p < P_DIM; ++p) {
            const float wa = wA[p], wb = wB[p];
            a0 += wa * v[p].x;
            a1 += (s1 ? wa : wb) * v[p].y;
            a2 += (s2 ? wa : wb) * v[p].z;
            a3 += (s3 ? wa : wb) * v[p].w;
        }

        float4 o = {0.5f * a0, 0.5f * a1, 0.5f * a2, 0.5f * a3};
        reinterpret_cast<float4*>(out)[(size_t)b * NTHR + tid] = o;
    }
}

extern "C" void kernel_launch(void* const* d_in, const int* in_sizes, int n_in,
                              void* d_out, int out_size)
{
    const float* t  = (const float*)d_in[0];   // [P,B,C,L]
    const float* na = (const float*)d_in[1];   // [B,Z]
    const float* W  = (const float*)d_in[2];   // [Z,C,P]
    float* out      = (float*)d_out;           // [B,C,L]

    const int B = in_sizes[1] / Z_DIM;

    // Persistent: 8 CTAs per SM on 148 SMs (GB300: 152; 148*8 is safe and
    // work-stealing fills any extras), grid-stride over nodes.
    int grid = 148 * NCTA_PER_SM;
    if (grid > B) grid = B;

    ecwl_kernel<<<grid, NTHR>>>(t, na, W, out, B);
}

// round 7
// speedup vs baseline: 1.0777x; 1.0777x over previous
#include <cuda_runtime.h>

// out[b,c,d] = 0.5 * sum_p W[z(b),c,p] * t[p,b,c,d]   (z(b) = one-hot argmax)
//   t:  [P=4, B, C=256, L=3] fp32   na: [B, Z=64] fp32   W: [Z=64, C=256, P=4]
//   out:[B, C=256, L=3]
//
// HBM-bound streamer (781 MB floor; best so far 111.1us @ 88.9% DRAM).
// R7: flat 384-thread CTA = 2 nodes side by side (threads 0-191 -> node 2b,
// 192-383 -> node 2b+1). Per-thread body identical to R5 (32 regs), occupancy
// unchanged (4x384 = 1536 thr/SM), grid halves to 25K. na load issued FIRST
// (head of the only dependency chain: na -> ballot -> W -> FMA -> store);
// t loads are independent leaves.

#define Z_DIM 64
#define C_DIM 256
#define P_DIM 4
#define L_DIM 3
#define CL    (C_DIM * L_DIM)   // 768 floats per (p,b) plane / out row
#define CP    (C_DIM * P_DIM)   // 1024 floats per W[z] row
#define NPT   (CL / 4)          // 192 threads per node
#define NTHR  (2 * NPT)         // 384 threads: two nodes per CTA, flat

__global__ void __launch_bounds__(NTHR)
ecwl_kernel(const float* __restrict__ t,
            const float* __restrict__ na,
            const float* __restrict__ W,
            float*       __restrict__ out,
            int B)
{
    const int tid   = threadIdx.x;
    const int node  = tid / NPT;            // 0 or 1 within CTA
    const int ltid  = tid - node * NPT;     // 0..191 within node
    const int lane  = tid & 31;
    const int b     = blockIdx.x * 2 + node;
    if (b >= B) return;                     // tail CTA (B odd)

    const int e0 = ltid * 4;

    // 1) Head of the dependency chain first: one-hot row loads (warp-local,
    //    each warp serves exactly one node since NPT is a multiple of 32).
    const float x0 = __ldg(na + (size_t)b * Z_DIM + lane);
    const float x1 = __ldg(na + (size_t)b * Z_DIM + 32 + lane);

    // 2) Independent t-plane loads fill the DRAM pipe while na resolves.
    float4 v[P_DIM];
    #pragma unroll
    for (int p = 0; p < P_DIM; ++p)
        v[p] = *reinterpret_cast<const float4*>(
            t + ((size_t)p * B + b) * CL + e0);

    // 3) Ballot-based routing resolve (no barrier, no smem).
    const unsigned m0 = __ballot_sync(0xFFFFFFFFu, x0 > 0.5f);
    const unsigned m1 = __ballot_sync(0xFFFFFFFFu, x1 > 0.5f);
    const int zi = m0 ? (__ffs(m0) - 1) : (32 + __ffs(m1) - 1);

    // 4) Weight row (L1/L2-hot: 64 rows, reused 50000x). float4 = the 4
    //    path-weights of one channel; a thread's t-float4 straddles <=2
    //    channels (L=3).
    const int c0 = e0 / 3;
    const float4* Wr = reinterpret_cast<const float4*>(W + (size_t)zi * CP);
    const float4 w0 = __ldg(Wr + c0);
    const float4 w1 = __ldg(Wr + c0 + 1);   // c0 <= 254, in-bounds

    const float wA[4] = {w0.x, w0.y, w0.z, w0.w};
    const float wB[4] = {w1.x, w1.y, w1.z, w1.w};

    const bool s1 = ((e0 + 1) / 3 == c0);
    const bool s2 = ((e0 + 2) / 3 == c0);
    const bool s3 = ((e0 + 3) / 3 == c0);

    float a0 = 0.f, a1 = 0.f, a2 = 0.f, a3 = 0.f;
    #pragma unroll
    for (int p = 0; p < P_DIM; ++p) {
        const float wa = wA[p], wb = wB[p];
        a0 += wa * v[p].x;
        a1 += (s1 ? wa : wb) * v[p].y;
        a2 += (s2 ? wa : wb) * v[p].z;
        a3 += (s3 ? wa : wb) * v[p].w;
    }

    float4 o = {0.5f * a0, 0.5f * a1, 0.5f * a2, 0.5f * a3};
    reinterpret_cast<float4*>(out)[(size_t)b * NPT + ltid] = o;
}

extern "C" void kernel_launch(void* const* d_in, const int* in_sizes, int n_in,
                              void* d_out, int out_size)
{
    const float* t  = (const float*)d_in[0];   // [P,B,C,L]
    const float* na = (const float*)d_in[1];   // [B,Z]
    const float* W  = (const float*)d_in[2];   // [Z,C,P]
    float* out      = (float*)d_out;           // [B,C,L]

    const int B = in_sizes[1] / Z_DIM;
    const int grid = (B + 1) / 2;

    ecwl_kernel<<<grid, NTHR>>>(t, na, W, out, B);
}

// round 8
// speedup vs baseline: 1.0963x; 1.0173x over previous
#include <cuda_runtime.h>

// out[b,c,d] = 0.5 * sum_p W[z(b),c,p] * t[p,b,c,d]   (z(b) = one-hot argmax)
//   t:  [P=4, B, C=256, L=3] fp32   na: [B, Z=64] fp32   W: [Z=64, C=256, P=4]
//   out:[B, C=256, L=3]
//
// HBM-bound streamer (781 MB floor; best 111.1us @ 88.9% DRAM, R5 shape).
// R8 = R5 shape (1 node/CTA, 192 thr, 32 regs, grid=B) + micro-tweaks:
//   - na row read as ONE float2 per lane (64 vals / 32 lanes) -> one LDG and
//     one ballot fewer on the critical chain (na -> ballot -> W -> FMA -> st)
//   - na issued before the t loads (chain head first; t loads are leaves)

#define Z_DIM 64
#define C_DIM 256
#define P_DIM 4
#define L_DIM 3
#define CL    (C_DIM * L_DIM)   // 768 floats per (p,b) plane / out row
#define CP    (C_DIM * P_DIM)   // 1024 floats per W[z] row
#define NTHR  (CL / 4)          // 192 threads: one float4 per thread

__global__ void __launch_bounds__(NTHR)
ecwl_kernel(const float* __restrict__ t,
            const float* __restrict__ na,
            const float* __restrict__ W,
            float*       __restrict__ out,
            int B)
{
    const int b    = blockIdx.x;
    const int tid  = threadIdx.x;
    const int lane = tid & 31;
    const int e0   = tid * 4;

    // 1) Head of the dependency chain first: the one-hot row, one float2 per
    //    lane (fully coalesced 256B). Each warp resolves independently.
    const float2 x = __ldg(reinterpret_cast<const float2*>(na + (size_t)b * Z_DIM) + lane);

    // 2) Independent t-plane loads fill the DRAM pipe while na resolves.
    float4 v[P_DIM];
    #pragma unroll
    for (int p = 0; p < P_DIM; ++p)
        v[p] = *reinterpret_cast<const float4*>(
            t + ((size_t)p * B + b) * CL + e0);

    // 3) Ballot routing resolve: hot lane holds the pair (2z, 2z+1).
    const unsigned m = __ballot_sync(0xFFFFFFFFu, (x.x > 0.5f) | (x.y > 0.5f));
    const int hot    = __ffs(m) - 1;
    const float xy   = __shfl_sync(0xFFFFFFFFu, x.y, hot);
    const int zi     = 2 * hot + (xy > 0.5f);

    // 4) Weight row (L1/L2-hot: 64 rows, reused 50000x). float4 = the 4
    //    path-weights of one channel; a thread's t-float4 straddles <=2
    //    channels (L=3).
    const int c0 = e0 / 3;
    const float4* Wr = reinterpret_cast<const float4*>(W + (size_t)zi * CP);
    const float4 w0 = __ldg(Wr + c0);
    const float4 w1 = __ldg(Wr + c0 + 1);   // c0 <= 254, in-bounds

    const float wA[4] = {w0.x, w0.y, w0.z, w0.w};
    const float wB[4] = {w1.x, w1.y, w1.z, w1.w};

    const bool s1 = ((e0 + 1) / 3 == c0);
    const bool s2 = ((e0 + 2) / 3 == c0);
    const bool s3 = ((e0 + 3) / 3 == c0);

    float a0 = 0.f, a1 = 0.f, a2 = 0.f, a3 = 0.f;
    #pragma unroll
    for (int p = 0; p < P_DIM; ++p) {
        const float wa = wA[p], wb = wB[p];
        a0 += wa * v[p].x;
        a1 += (s1 ? wa : wb) * v[p].y;
        a2 += (s2 ? wa : wb) * v[p].z;
        a3 += (s3 ? wa : wb) * v[p].w;
    }

    float4 o = {0.5f * a0, 0.5f * a1, 0.5f * a2, 0.5f * a3};
    reinterpret_cast<float4*>(out)[(size_t)b * NTHR + tid] = o;
}

extern "C" void kernel_launch(void* const* d_in, const int* in_sizes, int n_in,
                              void* d_out, int out_size)
{
    const float* t  = (const float*)d_in[0];   // [P,B,C,L]
    const float* na = (const float*)d_in[1];   // [B,Z]
    const float* W  = (const float*)d_in[2];   // [Z,C,P]
    float* out      = (float*)d_out;           // [B,C,L]

    const int B = in_sizes[1] / Z_DIM;

    ecwl_kernel<<<B, NTHR>>>(t, na, W, out, B);
}